// round 12
// baseline (speedup 1.0000x reference)
#include <cuda_runtime.h>
#include <cuda_bf16.h>
#include <cstdint>

#define BATCH 128
#define CDIM 512
#define SDIM 128
#define MDIM 512
#define PAD 20    // B/ctx smem row stride (u32); 80B: 16B-aligned, conflict-free
#define APD 68    // scores A smem row stride (u32)

// ---------------- scratch (static device globals; no allocation) ----------------
__device__ __nv_bfloat16 g_xgh[BATCH * CDIM * SDIM];
__device__ __nv_bfloat16 g_xgl[BATCH * CDIM * SDIM];
__device__ __nv_bfloat16 g_keyh[BATCH * CDIM * SDIM];
__device__ __nv_bfloat16 g_keyl[BATCH * CDIM * SDIM];
__device__ __nv_bfloat16 g_vwfTh[BATCH * SDIM * CDIM]; // [b][s][c]
__device__ __nv_bfloat16 g_vwfTl[BATCH * SDIM * CDIM];
__device__ __nv_bfloat16 g_atth[(size_t)BATCH * CDIM * CDIM];
__device__ __nv_bfloat16 g_attl[(size_t)BATCH * CDIM * CDIM];
__device__ float g_gt[SDIM * SDIM];
__device__ float g_w[SDIM];
__device__ float g_weff[SDIM * SDIM];
__device__ float g_beff[SDIM];
__device__ float g_psum[CDIM * BATCH];
__device__ float g_psumsq[CDIM * BATCH];
__device__ float g_scale[CDIM];
__device__ float g_shift[CDIM];

// ---------------- helpers ----------------
__device__ __forceinline__ void split_bf16(float v, uint16_t& h, uint16_t& l) {
    __nv_bfloat16 hb = __float2bfloat16(v);
    h = *(uint16_t*)&hb;
    __nv_bfloat16 lb = __float2bfloat16(v - __bfloat162float(hb));
    l = *(uint16_t*)&lb;
}
__device__ __forceinline__ void split2(float a, float b, uint32_t& hw, uint32_t& lw) {
    uint16_t h0, l0, h1, l1;
    split_bf16(a, h0, l0);
    split_bf16(b, h1, l1);
    hw = (uint32_t)h0 | ((uint32_t)h1 << 16);
    lw = (uint32_t)l0 | ((uint32_t)l1 << 16);
}
__device__ __forceinline__ void mma16816(float* c, const uint32_t* a, uint32_t b0, uint32_t b1) {
    asm volatile(
        "mma.sync.aligned.m16n8k16.row.col.f32.bf16.bf16.f32 "
        "{%0,%1,%2,%3}, {%4,%5,%6,%7}, {%8,%9}, {%0,%1,%2,%3};\n"
        : "+f"(c[0]), "+f"(c[1]), "+f"(c[2]), "+f"(c[3])
        : "r"(a[0]), "r"(a[1]), "r"(a[2]), "r"(a[3]), "r"(b0), "r"(b1));
}
__device__ __forceinline__ void ldmx4(uint32_t* r, uint32_t addr) {
    asm volatile("ldmatrix.sync.aligned.m8n8.x4.shared.b16 {%0,%1,%2,%3}, [%4];"
        : "=r"(r[0]), "=r"(r[1]), "=r"(r[2]), "=r"(r[3]) : "r"(addr));
}
__device__ __forceinline__ uint32_t sptr(const void* p) {
    return (uint32_t)__cvta_generic_to_shared(p);
}
__device__ __forceinline__ void cpasync16(uint32_t dst, const void* src) {
    asm volatile("cp.async.cg.shared.global [%0], [%1], 16;" :: "r"(dst), "l"(src));
}
#define CP_COMMIT() asm volatile("cp.async.commit_group;" ::: "memory")
#define CP_WAIT1()  asm volatile("cp.async.wait_group 1;" ::: "memory")

// ---------------- K0: prep small matrices ----------------
__global__ void prep_kernel(const float* __restrict__ Wq, const float* __restrict__ bq,
                            const float* __restrict__ Wk, const float* __restrict__ bk,
                            const float* __restrict__ Wv, const float* __restrict__ bv,
                            const float* __restrict__ Wf, const float* __restrict__ bf) {
    const float SC = 0.04419417382415922f;   // 512^-0.5
    int n = blockIdx.x;
    int k = threadIdx.x;
    float g = 0.f, e = 0.f;
    for (int m = 0; m < MDIM; m++) {
        g += Wq[m * SDIM + k] * Wk[m * SDIM + n];
        e += Wf[n * MDIM + m] * Wv[m * SDIM + k];
    }
    g_gt[n * SDIM + k] = g * SC;
    g_weff[n * SDIM + k] = e;
    if (k == 0) {
        float w = 0.f, b = bf[n];
        for (int m = 0; m < MDIM; m++) {
            w += Wk[m * SDIM + n] * bq[m];
            b += Wf[n * MDIM + m] * bv[m];
        }
        g_w[n] = w * SC;
        g_beff[n] = b;
    }
}

// ---------------- K1: SIMT projection -> split-bf16 outputs ----------------
__global__ __launch_bounds__(256, 2) void proj_kernel(const float* __restrict__ X, int sel) {
    __shared__ float Xs[32][132];
    __shared__ float Ws[32][132];
    const float* W = (sel == 0) ? g_gt : g_weff;
    const float* bias = (sel == 0) ? g_w : g_beff;

    int tx = threadIdx.x, ty = threadIdx.y;
    int tid = ty * 16 + tx;
    int row0 = blockIdx.y * 128;

    float acc[8][8];
    #pragma unroll
    for (int i = 0; i < 8; i++)
        #pragma unroll
        for (int j = 0; j < 8; j++) acc[i][j] = 0.f;

    for (int kc = 0; kc < 4; kc++) {
        __syncthreads();
        #pragma unroll
        for (int t = 0; t < 4; t++) {
            int f = tid + t * 256;
            int r = f >> 3;
            int k0 = (f & 7) * 4;
            float4 v = *(const float4*)(X + (size_t)(row0 + r) * SDIM + kc * 32 + k0);
            Xs[k0 + 0][r] = v.x; Xs[k0 + 1][r] = v.y; Xs[k0 + 2][r] = v.z; Xs[k0 + 3][r] = v.w;
            float4 w = *(const float4*)(W + (size_t)r * SDIM + kc * 32 + k0);
            Ws[k0 + 0][r] = w.x; Ws[k0 + 1][r] = w.y; Ws[k0 + 2][r] = w.z; Ws[k0 + 3][r] = w.w;
        }
        __syncthreads();
        #pragma unroll
        for (int k = 0; k < 32; k++) {
            float a[8], bb[8];
            *(float4*)(a)      = *(const float4*)&Xs[k][ty * 8];
            *(float4*)(a + 4)  = *(const float4*)&Xs[k][ty * 8 + 4];
            *(float4*)(bb)     = *(const float4*)&Ws[k][tx * 8];
            *(float4*)(bb + 4) = *(const float4*)&Ws[k][tx * 8 + 4];
            #pragma unroll
            for (int i = 0; i < 8; i++)
                #pragma unroll
                for (int j = 0; j < 8; j++) acc[i][j] += a[i] * bb[j];
        }
    }

    float bvv[8];
    #pragma unroll
    for (int j = 0; j < 8; j++) bvv[j] = bias[tx * 8 + j];
    #pragma unroll
    for (int i = 0; i < 8; i++)
        #pragma unroll
        for (int j = 0; j < 8; j++) acc[i][j] += bvv[j];

    if (sel == 0) {
        #pragma unroll
        for (int i = 0; i < 8; i++) {
            int row = row0 + ty * 8 + i;
            uint32_t hw[4], lw[4];
            #pragma unroll
            for (int q = 0; q < 4; q++)
                split2(acc[i][2 * q], acc[i][2 * q + 1], hw[q], lw[q]);
            *(uint4*)(g_xgh + (size_t)row * SDIM + tx * 8) = make_uint4(hw[0], hw[1], hw[2], hw[3]);
            *(uint4*)(g_xgl + (size_t)row * SDIM + tx * 8) = make_uint4(lw[0], lw[1], lw[2], lw[3]);
        }
    } else {
        int b = row0 >> 9;
        int c0 = (row0 & 511) + ty * 8;
        #pragma unroll
        for (int j = 0; j < 8; j++) {
            int s = tx * 8 + j;
            uint32_t hw[4], lw[4];
            #pragma unroll
            for (int q = 0; q < 4; q++)
                split2(acc[2 * q][j], acc[2 * q + 1][j], hw[q], lw[q]);
            size_t base = ((size_t)b * SDIM + s) * CDIM + c0;
            *(uint4*)(g_vwfTh + base) = make_uint4(hw[0], hw[1], hw[2], hw[3]);
            *(uint4*)(g_vwfTl + base) = make_uint4(lw[0], lw[1], lw[2], lw[3]);
        }
    }
}

// ---------------- K2: split key into bf16 hi/lo ----------------
__global__ void keysplit_kernel(const float* __restrict__ key) {
    int idx = blockIdx.x * 256 + threadIdx.x;
    float4 v = ((const float4*)key)[idx];
    uint32_t h0, l0, h1, l1;
    split2(v.x, v.y, h0, l0);
    split2(v.z, v.w, h1, l1);
    ((uint2*)g_keyh)[idx] = make_uint2(h0, h1);
    ((uint2*)g_keyl)[idx] = make_uint2(l0, l1);
}

// ---------------- K3: fused scores + softmax (cp.async 2-stage, 64 rows) ----------------
// block: 64 q-rows x ALL 512 cols. 512 threads, warp tile 32x64.
__global__ __launch_bounds__(512, 1) void scores_mma(float* __restrict__ att) {
    extern __shared__ uint32_t smem[];
    uint32_t* Ah = smem;                              // 64 x APD
    uint32_t* Al = Ah + 64 * APD;
    uint32_t* Bbuf = Al + 64 * APD;                   // 2 stages x {h,l} x 512*PAD
    float* red = (float*)(Bbuf + 2 * 2 * 512 * PAD);  // [64][8]

    int tid = threadIdx.x, lane = tid & 31, wid = tid >> 5;
    int wm = wid & 1, wn = wid >> 1;                  // 2 row-groups x 8 col-groups
    int b = blockIdx.y, i0 = blockIdx.x * 64;

    uint32_t ahb = sptr(Ah), alb = sptr(Al), bbase = sptr(Bbuf);
    const uint32_t stage_u32 = 2 * 512 * PAD;         // u32 per stage (h+l)

    // A: 64 rows x 16 uint4, h and l
    #pragma unroll
    for (int t = 0; t < 2; t++) {
        int f = tid + t * 512;                        // 0..1023
        int row = f >> 4, q = f & 15;
        size_t so = (size_t)(b * CDIM + i0 + row) * SDIM + q * 8;
        *(uint4*)&Ah[row * APD + q * 4] = *(const uint4*)(g_xgh + so);
        *(uint4*)&Al[row * APD + q * 4] = *(const uint4*)(g_xgl + so);
    }

    // issue B chunk kc into stage s (512 rows x 4 uint4, h and l)
    auto issueB = [&](int kc, int s) {
        uint32_t hs = bbase + (s * stage_u32) * 4;
        uint32_t ls = hs + 512 * PAD * 4;
        #pragma unroll
        for (int t = 0; t < 4; t++) {
            int f = tid + t * 512;                    // 0..2047
            int row = f >> 2, q = f & 3;
            size_t so = (size_t)(b * CDIM + row) * SDIM + kc * 32 + q * 8;
            uint32_t doff = (uint32_t)(row * PAD + q * 4) * 4;
            cpasync16(hs + doff, g_keyh + so);
            cpasync16(ls + doff, g_keyl + so);
        }
    };

    float acc[2][8][4];
    #pragma unroll
    for (int mt = 0; mt < 2; mt++)
        #pragma unroll
        for (int nt = 0; nt < 8; nt++)
            #pragma unroll
            for (int q = 0; q < 4; q++) acc[mt][nt][q] = 0.f;

    uint32_t a_row = ((lane >> 3) & 1) * 8 + (lane & 7);
    uint32_t a_koff = (lane >> 4) * 16;
    uint32_t b_nrow = ((lane >> 4) & 1) * 8 + (lane & 7);
    uint32_t b_koff = ((lane >> 3) & 1) * 16;

    issueB(0, 0); CP_COMMIT();
    issueB(1, 1); CP_COMMIT();

    #pragma unroll
    for (int kc = 0; kc < 4; kc++) {
        CP_WAIT1();
        __syncthreads();
        int s = kc & 1;
        uint32_t bhb = bbase + (s * stage_u32) * 4;
        uint32_t blb = bhb + 512 * PAD * 4;
        #pragma unroll
        for (int ks = 0; ks < 2; ks++) {
            uint32_t kbA = (uint32_t)(kc * 32 + ks * 16) * 2 + a_koff;
            uint32_t kbB = (uint32_t)(ks * 16) * 2 + b_koff;
            uint32_t ah[2][4], al[2][4];
            #pragma unroll
            for (int mt = 0; mt < 2; mt++) {
                uint32_t ro = (wm * 32 + mt * 16 + a_row) * (APD * 4);
                ldmx4(ah[mt], ahb + ro + kbA);
                ldmx4(al[mt], alb + ro + kbA);
            }
            #pragma unroll
            for (int np = 0; np < 4; np++) {
                uint32_t no = (wn * 64 + np * 16 + b_nrow) * (PAD * 4);
                uint32_t bh[4], bl[4];
                ldmx4(bh, bhb + no + kbB);
                ldmx4(bl, blb + no + kbB);
                #pragma unroll
                for (int half = 0; half < 2; half++) {
                    int nt = np * 2 + half;
                    uint32_t h0 = bh[half * 2], h1 = bh[half * 2 + 1];
                    uint32_t l0 = bl[half * 2], l1 = bl[half * 2 + 1];
                    #pragma unroll
                    for (int mt = 0; mt < 2; mt++) {
                        mma16816(acc[mt][nt], ah[mt], h0, h1);
                        mma16816(acc[mt][nt], ah[mt], l0, l1);
                        mma16816(acc[mt][nt], al[mt], h0, h1);
                    }
                }
            }
        }
        __syncthreads();
        if (kc + 2 < 4) issueB(kc + 2, s);
        CP_COMMIT();                                   // empty group when no issue
    }

    // exp (no max-subtract: |logit| small; identical after normalization)
    #pragma unroll
    for (int mt = 0; mt < 2; mt++)
        #pragma unroll
        for (int nt = 0; nt < 8; nt++)
            #pragma unroll
            for (int q = 0; q < 4; q++) acc[mt][nt][q] = __expf(acc[mt][nt][q]);

    // per-warp row sums over its 64 cols
    #pragma unroll
    for (int mt = 0; mt < 2; mt++) {
        float s0 = 0.f, s8 = 0.f;
        #pragma unroll
        for (int nt = 0; nt < 8; nt++) {
            s0 += acc[mt][nt][0] + acc[mt][nt][1];
            s8 += acc[mt][nt][2] + acc[mt][nt][3];
        }
        #pragma unroll
        for (int off = 1; off <= 2; off <<= 1) {
            s0 += __shfl_xor_sync(0xffffffffu, s0, off);
            s8 += __shfl_xor_sync(0xffffffffu, s8, off);
        }
        if ((lane & 3) == 0) {
            int r = wm * 32 + mt * 16 + (lane >> 2);
            red[r * 8 + wn] = s0;
            red[(r + 8) * 8 + wn] = s8;
        }
    }
    __syncthreads();

    // normalize + write fp32 att AND bf16 h/l att
    #pragma unroll
    for (int mt = 0; mt < 2; mt++) {
        int r0 = wm * 32 + mt * 16 + (lane >> 2);
        float t0 = 0.f, t8 = 0.f;
        #pragma unroll
        for (int w = 0; w < 8; w++) { t0 += red[r0 * 8 + w]; t8 += red[(r0 + 8) * 8 + w]; }
        float inv0 = 1.0f / t0, inv8 = 1.0f / t8;
        size_t rowb = (size_t)b * CDIM + i0 + r0;
        float* p0 = att + rowb * CDIM;
        __nv_bfloat16* h0p = g_atth + rowb * CDIM;
        __nv_bfloat16* l0p = g_attl + rowb * CDIM;
        #pragma unroll
        for (int nt = 0; nt < 8; nt++) {
            int gcol = wn * 64 + nt * 8 + (lane & 3) * 2;
            float v0 = acc[mt][nt][0] * inv0, v1 = acc[mt][nt][1] * inv0;
            float v2 = acc[mt][nt][2] * inv8, v3 = acc[mt][nt][3] * inv8;
            *(float2*)(p0 + gcol) = make_float2(v0, v1);
            *(float2*)(p0 + 8 * CDIM + gcol) = make_float2(v2, v3);
            uint32_t hw, lw;
            split2(v0, v1, hw, lw);
            *(uint32_t*)(h0p + gcol) = hw;
            *(uint32_t*)(l0p + gcol) = lw;
            split2(v2, v3, hw, lw);
            *(uint32_t*)(h0p + 8 * CDIM + gcol) = hw;
            *(uint32_t*)(l0p + 8 * CDIM + gcol) = lw;
        }
    }
}

// ---------------- K4: context GEMM (cp.async 2-stage, pre-split A) + BN partials ----------------
__global__ __launch_bounds__(256, 2) void ctx_mma(float* __restrict__ outp) {
    extern __shared__ uint32_t smem[];
    // stage s: Ah, Al, Bh, Bl each 128*PAD u32
    uint32_t* base = smem;
    float* redS = (float*)(base + 2 * 4 * 128 * PAD);      // [128][2]
    float* redQ = redS + 256;

    int tid = threadIdx.x, lane = tid & 31, wid = tid >> 5;
    int wm = wid & 3, wn = wid >> 2;
    int b = blockIdx.y, c0 = blockIdx.x * 128;

    uint32_t sb = sptr(base);
    const uint32_t arr = 128 * PAD;                        // u32 per array
    const uint32_t stage_u32 = 4 * arr;

    auto issue = [&](int kc, int s) {
        uint32_t ah = sb + (s * stage_u32) * 4;
        uint32_t al = ah + arr * 4;
        uint32_t bh = al + arr * 4;
        uint32_t bl = bh + arr * 4;
        #pragma unroll
        for (int t = 0; t < 2; t++) {
            int f = tid + t * 256;                         // 0..511
            int row = f >> 2, q = f & 3;
            uint32_t doff = (uint32_t)(row * PAD + q * 4) * 4;
            size_t aso = ((size_t)b * CDIM + c0 + row) * CDIM + kc * 32 + q * 8;
            cpasync16(ah + doff, g_atth + aso);
            cpasync16(al + doff, g_attl + aso);
            size_t bso = ((size_t)b * SDIM + row) * CDIM + kc * 32 + q * 8;
            cpasync16(bh + doff, g_vwfTh + bso);
            cpasync16(bl + doff, g_vwfTl + bso);
        }
    };

    float acc[2][8][4];
    #pragma unroll
    for (int mt = 0; mt < 2; mt++)
        #pragma unroll
        for (int nt = 0; nt < 8; nt++)
            #pragma unroll
            for (int q = 0; q < 4; q++) acc[mt][nt][q] = 0.f;

    uint32_t a_row = ((lane >> 3) & 1) * 8 + (lane & 7);
    uint32_t a_koff = (lane >> 4) * 16;
    uint32_t b_nrow = ((lane >> 4) & 1) * 8 + (lane & 7);
    uint32_t b_koff = ((lane >> 3) & 1) * 16;

    issue(0, 0); CP_COMMIT();
    issue(1, 1); CP_COMMIT();

    for (int kc = 0; kc < 16; kc++) {
        CP_WAIT1();
        __syncthreads();
        int s = kc & 1;
        uint32_t ahb = sb + (s * stage_u32) * 4;
        uint32_t alb = ahb + arr * 4;
        uint32_t bhb = alb + arr * 4;
        uint32_t blb = bhb + arr * 4;
        #pragma unroll
        for (int ks = 0; ks < 2; ks++) {
            uint32_t kb = (uint32_t)(ks * 16) * 2;
            uint32_t ah[2][4], al[2][4];
            #pragma unroll
            for (int mt = 0; mt < 2; mt++) {
                uint32_t ro = (wm * 32 + mt * 16 + a_row) * (PAD * 4);
                ldmx4(ah[mt], ahb + ro + kb + a_koff);
                ldmx4(al[mt], alb + ro + kb + a_koff);
            }
            #pragma unroll
            for (int np = 0; np < 4; np++) {
                uint32_t no = (wn * 64 + np * 16 + b_nrow) * (PAD * 4);
                uint32_t bh[4], bl[4];
                ldmx4(bh, bhb + no + kb + b_koff);
                ldmx4(bl, blb + no + kb + b_koff);
                #pragma unroll
                for (int half = 0; half < 2; half++) {
                    int nt = np * 2 + half;
                    uint32_t h0 = bh[half * 2], h1 = bh[half * 2 + 1];
                    uint32_t l0 = bl[half * 2], l1 = bl[half * 2 + 1];
                    #pragma unroll
                    for (int mt = 0; mt < 2; mt++) {
                        mma16816(acc[mt][nt], ah[mt], h0, h1);
                        mma16816(acc[mt][nt], ah[mt], l0, l1);
                        mma16816(acc[mt][nt], al[mt], h0, h1);
                    }
                }
            }
        }
        __syncthreads();
        if (kc + 2 < 16) issue(kc + 2, s);
        CP_COMMIT();
    }

    // write output + per-row BN partial sums
    #pragma unroll
    for (int mt = 0; mt < 2; mt++) {
        int grow = c0 + wm * 32 + mt * 16 + (lane >> 2);
        float sA = 0.f, qA = 0.f, sB = 0.f, qB = 0.f;
        #pragma unroll
        for (int nt = 0; nt < 8; nt++) {
            int gcol = wn * 64 + nt * 8 + (lane & 3) * 2;
            float* p = outp + ((size_t)b * CDIM + grow) * SDIM + gcol;
            float v0 = acc[mt][nt][0], v1 = acc[mt][nt][1];
            float v2 = acc[mt][nt][2], v3 = acc[mt][nt][3];
            *(float2*)p = make_float2(v0, v1);
            *(float2*)(p + 8 * SDIM) = make_float2(v2, v3);
            sA += v0 + v1; qA += v0 * v0 + v1 * v1;
            sB += v2 + v3; qB += v2 * v2 + v3 * v3;
        }
        #pragma unroll
        for (int off = 1; off <= 2; off <<= 1) {
            sA += __shfl_xor_sync(0xffffffffu, sA, off);
            qA += __shfl_xor_sync(0xffffffffu, qA, off);
            sB += __shfl_xor_sync(0xffffffffu, sB, off);
            qB += __shfl_xor_sync(0xffffffffu, qB, off);
        }
        if ((lane & 3) == 0) {
            int lr = wm * 32 + mt * 16 + (lane >> 2);
            redS[lr * 2 + wn] = sA;       redQ[lr * 2 + wn] = qA;
            redS[(lr + 8) * 2 + wn] = sB; redQ[(lr + 8) * 2 + wn] = qB;
        }
    }
    __syncthreads();
    if (tid < 128) {
        int c = c0 + tid;
        g_psum[(size_t)c * BATCH + b] = redS[tid * 2] + redS[tid * 2 + 1];
        g_psumsq[(size_t)c * BATCH + b] = redQ[tid * 2] + redQ[tid * 2 + 1];
    }
}

// ---------------- K5: finalize BN stats ----------------
__global__ void stats_kernel(const float* __restrict__ gamma, const float* __restrict__ beta) {
    int c = threadIdx.x;
    float s = 0.f, ss = 0.f;
    for (int b = 0; b < BATCH; b++) {
        s += g_psum[(size_t)c * BATCH + b];
        ss += g_psumsq[(size_t)c * BATCH + b];
    }
    const float inv_n = 1.0f / (float)(BATCH * SDIM);
    float mean = s * inv_n;
    float var = ss * inv_n - mean * mean;
    float sc = gamma[c] * rsqrtf(var + 1e-5f);
    g_scale[c] = sc;
    g_shift[c] = beta[c] - mean * sc;
}

// ---------------- K6: apply BN + relu + residual ----------------
__global__ void apply_kernel(const float* __restrict__ value, float* __restrict__ out) {
    int idx = blockIdx.x * 256 + threadIdx.x;
    int c = (idx >> 5) & (CDIM - 1);
    float sc = g_scale[c], sh = g_shift[c];
    float4 o = ((const float4*)out)[idx];
    float4 v = ((const float4*)value)[idx];
    o.x = fmaxf(o.x * sc + sh, 0.f) + v.x;
    o.y = fmaxf(o.y * sc + sh, 0.f) + v.y;
    o.z = fmaxf(o.z * sc + sh, 0.f) + v.z;
    o.w = fmaxf(o.w * sc + sh, 0.f) + v.w;
    ((float4*)out)[idx] = o;
}

// ---------------- launch ----------------
extern "C" void kernel_launch(void* const* d_in, const int* in_sizes, int n_in,
                              void* d_out, int out_size) {
    const float* query = (const float*)d_in[0];
    const float* key   = (const float*)d_in[1];
    const float* value = (const float*)d_in[2];
    const float* Wq = (const float*)d_in[3];
    const float* bq = (const float*)d_in[4];
    const float* Wk = (const float*)d_in[5];
    const float* bk = (const float*)d_in[6];
    const float* Wv = (const float*)d_in[7];
    const float* bv = (const float*)d_in[8];
    const float* Wf = (const float*)d_in[9];
    const float* bf = (const float*)d_in[10];
    const float* gamma = (const float*)d_in[11];
    const float* beta  = (const float*)d_in[12];

    float* out = (float*)d_out;                               // [B,C,S]
    float* att = out + (size_t)BATCH * CDIM * SDIM;           // [B,C,C]

    int scores_smem = (2 * 64 * APD + 2 * 2 * 512 * PAD + 64 * 8) * 4;
    cudaFuncSetAttribute(scores_mma, cudaFuncAttributeMaxDynamicSharedMemorySize, scores_smem);
    int ctx_smem = (2 * 4 * 128 * PAD) * 4 + 2 * 256 * 4;
    cudaFuncSetAttribute(ctx_mma, cudaFuncAttributeMaxDynamicSharedMemorySize, ctx_smem);

    dim3 blk(16, 16);
    prep_kernel<<<SDIM, SDIM>>>(Wq, bq, Wk, bk, Wv, bv, Wf, bf);
    proj_kernel<<<dim3(1, 512), blk>>>(query, 0);
    proj_kernel<<<dim3(1, 512), blk>>>(value, 1);
    keysplit_kernel<<<8192, 256>>>(key);
    scores_mma<<<dim3(8, BATCH), 512, scores_smem>>>(att);
    ctx_mma<<<dim3(4, BATCH), 256, ctx_smem>>>(out);
    stats_kernel<<<1, CDIM>>>(gamma, beta);
    apply_kernel<<<8192, 256>>>(value, out);
}